// round 1
// baseline (speedup 1.0000x reference)
#include <cuda_runtime.h>
#include <cuda_bf16.h>

// Problem constants
#define B_TOT 2048
#define IFEAT 256
#define OFEAT 512
#define NSEG  8
#define LN_EPS 1e-5f

// Tiling
#define TB 64     // batch rows per block
#define TO 128    // output cols per block
#define IC 4      // features per staged chunk (32 vocab rows)
#define NCH (IFEAT / IC)   // 64 chunks
#define NTHREADS 512

// Scratch: normalized activations
__device__ float g_xn[B_TOT * IFEAT];

// ---------------------------------------------------------------------------
// Kernel 1: LayerNorm (two-pass, matching reference numerics) -> g_xn
// one block per batch row, 256 threads
// ---------------------------------------------------------------------------
__global__ __launch_bounds__(IFEAT) void ln_kernel(
    const float* __restrict__ x,
    const float* __restrict__ gamma,
    const float* __restrict__ beta)
{
    const int b = blockIdx.x;
    const int t = threadIdx.x;
    __shared__ float red[IFEAT / 32];

    float v = x[b * IFEAT + t];

    // mean
    float s = v;
    #pragma unroll
    for (int o = 16; o > 0; o >>= 1) s += __shfl_xor_sync(0xFFFFFFFFu, s, o);
    if ((t & 31) == 0) red[t >> 5] = s;
    __syncthreads();
    float tot = 0.f;
    #pragma unroll
    for (int w = 0; w < IFEAT / 32; w++) tot += red[w];
    const float mu = tot * (1.0f / IFEAT);
    __syncthreads();

    // variance (of deviations, like reference)
    const float d = v - mu;
    float s2 = d * d;
    #pragma unroll
    for (int o = 16; o > 0; o >>= 1) s2 += __shfl_xor_sync(0xFFFFFFFFu, s2, o);
    if ((t & 31) == 0) red[t >> 5] = s2;
    __syncthreads();
    float tv = 0.f;
    #pragma unroll
    for (int w = 0; w < IFEAT / 32; w++) tv += red[w];
    const float var = tv * (1.0f / IFEAT);

    const float xn = d * rsqrtf(var + LN_EPS) * gamma[t] + beta[t];
    g_xn[b * IFEAT + t] = xn;
}

// ---------------------------------------------------------------------------
// Kernel 2: contraction
//   y[b,o] = sum_i xn[b,i] * A[i*8+seg(b,i), o] + B[i*8+seg(b,i), o]
// Block: TB=64 batch rows x TO=128 outputs. 512 threads:
//   tx = t&31  -> 4 outputs (float4)
//   ty = t>>5  -> 4 batch rows (ty*4 + r)
// SMEM stages the 8-segment window for IC=4 features (32 vocab rows) of A and B.
// ---------------------------------------------------------------------------
__global__ __launch_bounds__(NTHREADS) void contract_kernel(
    const float* __restrict__ Aw,
    const float* __restrict__ Bw,
    float* __restrict__ y)
{
    __shared__ float4 a_s[IC * NSEG * (TO / 4)];  // 1024 float4 = 16 KB
    __shared__ float4 b_s[IC * NSEG * (TO / 4)];  // 16 KB
    __shared__ float4 xn_s[TB];                    // 1 KB: xn[row][ic 0..3]

    const int t  = threadIdx.x;
    const int tx = t & 31;
    const int ty = t >> 5;
    const int ob = blockIdx.x * TO;
    const int b0 = blockIdx.y * TB;

    float4 acc[4];
    #pragma unroll
    for (int r = 0; r < 4; r++) acc[r] = make_float4(0.f, 0.f, 0.f, 0.f);

    // prefetch registers
    float4 ra0, ra1, rb0, rb1, rx;

    // ---- prefetch chunk 0 ----
    {
        const int ch = 0;
        const float* pa0 = Aw + (size_t)(ch * 32 + ty)      * OFEAT + ob + tx * 4;
        const float* pa1 = Aw + (size_t)(ch * 32 + 16 + ty) * OFEAT + ob + tx * 4;
        const float* pb0 = Bw + (size_t)(ch * 32 + ty)      * OFEAT + ob + tx * 4;
        const float* pb1 = Bw + (size_t)(ch * 32 + 16 + ty) * OFEAT + ob + tx * 4;
        ra0 = *(const float4*)pa0;  ra1 = *(const float4*)pa1;
        rb0 = *(const float4*)pb0;  rb1 = *(const float4*)pb1;
        if (t < TB) rx = *(const float4*)&g_xn[(size_t)(b0 + t) * IFEAT + ch * IC];
    }

    for (int ch = 0; ch < NCH; ch++) {
        __syncthreads();  // previous compute done, smem free
        a_s[t]       = ra0;
        a_s[t + 512] = ra1;
        b_s[t]       = rb0;
        b_s[t + 512] = rb1;
        if (t < TB) xn_s[t] = rx;

        if (ch + 1 < NCH) {
            const int cn = ch + 1;
            const float* pa0 = Aw + (size_t)(cn * 32 + ty)      * OFEAT + ob + tx * 4;
            const float* pa1 = Aw + (size_t)(cn * 32 + 16 + ty) * OFEAT + ob + tx * 4;
            const float* pb0 = Bw + (size_t)(cn * 32 + ty)      * OFEAT + ob + tx * 4;
            const float* pb1 = Bw + (size_t)(cn * 32 + 16 + ty) * OFEAT + ob + tx * 4;
            ra0 = *(const float4*)pa0;  ra1 = *(const float4*)pa1;
            rb0 = *(const float4*)pb0;  rb1 = *(const float4*)pb1;
            if (t < TB) rx = *(const float4*)&g_xn[(size_t)(b0 + t) * IFEAT + cn * IC];
        }
        __syncthreads();  // staged data visible

        #pragma unroll
        for (int ic = 0; ic < IC; ic++) {
            #pragma unroll
            for (int r = 0; r < 4; r++) {
                const int row = ty * 4 + r;                    // warp-uniform
                const float xv = ((const float*)&xn_s[row])[ic];
                float fi = (xv + 1.0f) * 4.0f;                 // (xn - GRID_MIN)/STEP
                int sidx = (int)fi;                            // trunc toward zero
                sidx = sidx < 0 ? 0 : (sidx > NSEG - 1 ? NSEG - 1 : sidx);
                const int base = (ic * NSEG + sidx) * (TO / 4) + tx;
                const float4 a4 = a_s[base];
                const float4 b4 = b_s[base];
                acc[r].x = fmaf(xv, a4.x, acc[r].x + b4.x);
                acc[r].y = fmaf(xv, a4.y, acc[r].y + b4.y);
                acc[r].z = fmaf(xv, a4.z, acc[r].z + b4.z);
                acc[r].w = fmaf(xv, a4.w, acc[r].w + b4.w);
            }
        }
    }

    #pragma unroll
    for (int r = 0; r < 4; r++) {
        const int row = ty * 4 + r;
        *(float4*)&y[(size_t)(b0 + row) * OFEAT + ob + tx * 4] = acc[r];
    }
}

// ---------------------------------------------------------------------------
// Launch
// inputs (metadata order): x [2048*256], a_weight [2048*512], b_weight [2048*512],
//                          gamma [256], beta [256]; output fp32 [2048*512]
// ---------------------------------------------------------------------------
extern "C" void kernel_launch(void* const* d_in, const int* in_sizes, int n_in,
                              void* d_out, int out_size)
{
    const float* x     = (const float*)d_in[0];
    const float* a_w   = (const float*)d_in[1];
    const float* b_w   = (const float*)d_in[2];
    const float* gamma = (const float*)d_in[3];
    const float* beta  = (const float*)d_in[4];
    float* y = (float*)d_out;

    ln_kernel<<<B_TOT, IFEAT>>>(x, gamma, beta);

    dim3 grid(OFEAT / TO, B_TOT / TB);   // (4, 32) = 128 blocks
    contract_kernel<<<grid, NTHREADS>>>(a_w, b_w, y);
}

// round 2
// speedup vs baseline: 1.2420x; 1.2420x over previous
#include <cuda_runtime.h>
#include <cuda_fp16.h>

// Problem constants
#define B_TOT 2048
#define IFEAT 256
#define OFEAT 512
#define NSEG  8
#define LN_EPS 1e-5f

// Tiling
#define TB 64              // batch rows per block
#define TO 64              // output cols per block
#define IC 8               // features per staged chunk (64 vocab rows)
#define NCH (IFEAT / IC)   // 32 chunks
#define NTHREADS 512

// Scratch: normalized activations
__device__ float g_xn[B_TOT * IFEAT];

static __device__ __forceinline__ unsigned h2u(__half2 h) { return *reinterpret_cast<unsigned*>(&h); }
static __device__ __forceinline__ __half2 u2h(unsigned u) { return *reinterpret_cast<__half2*>(&u); }

// ---------------------------------------------------------------------------
// Kernel 1: LayerNorm (two-pass, matching reference numerics) -> g_xn
// ---------------------------------------------------------------------------
__global__ __launch_bounds__(IFEAT) void ln_kernel(
    const float* __restrict__ x,
    const float* __restrict__ gamma,
    const float* __restrict__ beta)
{
    const int b = blockIdx.x;
    const int t = threadIdx.x;
    __shared__ float red[IFEAT / 32];

    float v = x[b * IFEAT + t];

    float s = v;
    #pragma unroll
    for (int o = 16; o > 0; o >>= 1) s += __shfl_xor_sync(0xFFFFFFFFu, s, o);
    if ((t & 31) == 0) red[t >> 5] = s;
    __syncthreads();
    float tot = 0.f;
    #pragma unroll
    for (int w = 0; w < IFEAT / 32; w++) tot += red[w];
    const float mu = tot * (1.0f / IFEAT);
    __syncthreads();

    const float d = v - mu;
    float s2 = d * d;
    #pragma unroll
    for (int o = 16; o > 0; o >>= 1) s2 += __shfl_xor_sync(0xFFFFFFFFu, s2, o);
    if ((t & 31) == 0) red[t >> 5] = s2;
    __syncthreads();
    float tv = 0.f;
    #pragma unroll
    for (int w = 0; w < IFEAT / 32; w++) tv += red[w];
    const float var = tv * (1.0f / IFEAT);

    const float xn = d * rsqrtf(var + LN_EPS) * gamma[t] + beta[t];
    g_xn[b * IFEAT + t] = xn;
}

// ---------------------------------------------------------------------------
// Kernel 2: contraction with fp16-packed SMEM staging.
//   One uint4 in SMEM = {a0,a1,a2,a3,b0,b1,b2,b3} as halves for one
//   (vocab-row, output-quad). Inner loop: 1 LDS.128 per (row,i) instead of
//   2 fp32 LDS.128 -> half the SMEM-crossbar traffic.
// Block: TB=64 rows x TO=64 outputs, 512 threads.
//   tx = t&15  -> output quad (16 quads = 64 outputs)
//   ty = t>>4  -> 2 batch rows (ty*2 + r)
// ---------------------------------------------------------------------------
__global__ __launch_bounds__(NTHREADS, 2) void contract_kernel(
    const float* __restrict__ Aw,
    const float* __restrict__ Bw,
    float* __restrict__ y)
{
    __shared__ uint4  ab_s[IC * NSEG * (TO / 4)];   // 1024 uint4 = 16 KB
    __shared__ float4 xn_s[TB * IC / 4];            // 128 float4 = 2 KB

    const int t  = threadIdx.x;
    const int tx = t & 15;
    const int ty = t >> 4;
    const int ob = blockIdx.x * TO;
    const int b0 = blockIdx.y * TB;

    float  acc[2][4];
    __half2 accb[2][2];
    #pragma unroll
    for (int r = 0; r < 2; r++) {
        #pragma unroll
        for (int j = 0; j < 4; j++) acc[r][j] = 0.f;
        accb[r][0] = __float2half2_rn(0.f);
        accb[r][1] = __float2half2_rn(0.f);
    }

    float4 pa[2], pb[2], px;

    // ---- prefetch chunk 0 ----
    {
        #pragma unroll
        for (int s = 0; s < 2; s++) {
            const int slot = t + s * NTHREADS;       // 0..1023
            const int row  = slot >> 4;              // vocab row in chunk (0..63)
            const int o4   = slot & 15;
            const size_t g = (size_t)row * OFEAT + ob + o4 * 4;
            pa[s] = *(const float4*)(Aw + g);
            pb[s] = *(const float4*)(Bw + g);
        }
        if (t < TB * IC / 4) {
            const int row = t >> 1, part = t & 1;
            px = *(const float4*)&g_xn[(size_t)(b0 + row) * IFEAT + part * 4];
        }
    }

    for (int ch = 0; ch < NCH; ch++) {
        __syncthreads();   // previous compute done, smem reusable
        // stage (convert fp32 -> packed fp16)
        #pragma unroll
        for (int s = 0; s < 2; s++) {
            const int slot = t + s * NTHREADS;
            uint4 u;
            u.x = h2u(__floats2half2_rn(pa[s].x, pa[s].y));
            u.y = h2u(__floats2half2_rn(pa[s].z, pa[s].w));
            u.z = h2u(__floats2half2_rn(pb[s].x, pb[s].y));
            u.w = h2u(__floats2half2_rn(pb[s].z, pb[s].w));
            ab_s[slot] = u;
        }
        if (t < TB * IC / 4) xn_s[t] = px;

        // prefetch next chunk
        if (ch + 1 < NCH) {
            const int cn = ch + 1;
            #pragma unroll
            for (int s = 0; s < 2; s++) {
                const int slot = t + s * NTHREADS;
                const int row  = slot >> 4;
                const int o4   = slot & 15;
                const size_t g = (size_t)(cn * IC * NSEG + row) * OFEAT + ob + o4 * 4;
                pa[s] = *(const float4*)(Aw + g);
                pb[s] = *(const float4*)(Bw + g);
            }
            if (t < TB * IC / 4) {
                const int row = t >> 1, part = t & 1;
                px = *(const float4*)&g_xn[(size_t)(b0 + row) * IFEAT + cn * IC + part * 4];
            }
        }
        __syncthreads();   // staged data visible

        // load my 2 rows' xn for this chunk into registers
        float xr[2][IC];
        #pragma unroll
        for (int r = 0; r < 2; r++) {
            const int row = ty * 2 + r;
            const float4 x0 = xn_s[row * 2 + 0];
            const float4 x1 = xn_s[row * 2 + 1];
            xr[r][0] = x0.x; xr[r][1] = x0.y; xr[r][2] = x0.z; xr[r][3] = x0.w;
            xr[r][4] = x1.x; xr[r][5] = x1.y; xr[r][6] = x1.z; xr[r][7] = x1.w;
        }

        #pragma unroll
        for (int ic = 0; ic < IC; ic++) {
            #pragma unroll
            for (int r = 0; r < 2; r++) {
                const float xv = xr[r][ic];
                float fi = fminf(fmaxf((xv + 1.0f) * 4.0f, 0.0f), 7.0f);
                const int sidx = (int)fi;                         // trunc (clamped)
                const uint4 u = ab_s[(ic * NSEG + sidx) * (TO / 4) + tx];
                const float2 fa01 = __half22float2(u2h(u.x));
                const float2 fa23 = __half22float2(u2h(u.y));
                acc[r][0] = fmaf(xv, fa01.x, acc[r][0]);
                acc[r][1] = fmaf(xv, fa01.y, acc[r][1]);
                acc[r][2] = fmaf(xv, fa23.x, acc[r][2]);
                acc[r][3] = fmaf(xv, fa23.y, acc[r][3]);
                accb[r][0] = __hadd2(accb[r][0], u2h(u.z));
                accb[r][1] = __hadd2(accb[r][1], u2h(u.w));
            }
        }

        // flush fp16 b-accumulators into fp32 every chunk (bounds fp16 error)
        #pragma unroll
        for (int r = 0; r < 2; r++) {
            const float2 f01 = __half22float2(accb[r][0]);
            const float2 f23 = __half22float2(accb[r][1]);
            acc[r][0] += f01.x; acc[r][1] += f01.y;
            acc[r][2] += f23.x; acc[r][3] += f23.y;
            accb[r][0] = __float2half2_rn(0.f);
            accb[r][1] = __float2half2_rn(0.f);
        }
    }

    #pragma unroll
    for (int r = 0; r < 2; r++) {
        const int row = ty * 2 + r;
        float4 o;
        o.x = acc[r][0]; o.y = acc[r][1]; o.z = acc[r][2]; o.w = acc[r][3];
        *(float4*)&y[(size_t)(b0 + row) * OFEAT + ob + tx * 4] = o;
    }
}

// ---------------------------------------------------------------------------
// Launch
// inputs: x [2048*256], a_weight [2048*512], b_weight [2048*512],
//         gamma [256], beta [256]; output fp32 [2048*512]
// ---------------------------------------------------------------------------
extern "C" void kernel_launch(void* const* d_in, const int* in_sizes, int n_in,
                              void* d_out, int out_size)
{
    const float* x     = (const float*)d_in[0];
    const float* a_w   = (const float*)d_in[1];
    const float* b_w   = (const float*)d_in[2];
    const float* gamma = (const float*)d_in[3];
    const float* beta  = (const float*)d_in[4];
    float* y = (float*)d_out;

    ln_kernel<<<B_TOT, IFEAT>>>(x, gamma, beta);

    dim3 grid(OFEAT / TO, B_TOT / TB);   // (8, 32) = 256 blocks
    contract_kernel<<<grid, NTHREADS>>>(a_w, b_w, y);
}

// round 4
// speedup vs baseline: 2.0455x; 1.6469x over previous
#include <cuda_runtime.h>
#include <cuda_fp16.h>
#include <cstdint>

// ---------------- problem constants ----------------
#define B_TOT 2048
#define IFEAT 256
#define OFEAT 512
#define NSEG  8
#define LN_EPS 1e-5f
#define VOCAB (IFEAT * NSEG)      // 2048
#define K2    (2 * VOCAB)         // 4096 (A-block + B-block)

// ---------------- GEMM config ----------------
#define TM 128                    // CTA M tile
#define TN 128                    // CTA N tile
#define KP 64                     // K per SMEM panel
#define KSPLIT 2
#define KCTA (K2 / KSPLIT)        // 2048
#define NP   (KCTA / KP)          // 32 panels
#define GT   256                  // gemm threads (8 warps)

#define AS_STRIDE 72              // halves per SMEM row (64 data + 8 pad)
#define AS_STRIDE_B (AS_STRIDE * 2)   // 144 bytes
#define STAGE_BYTES (128 * AS_STRIDE_B)   // 18432
#define SMEM_TOTAL (4 * STAGE_BYTES)      // A0,A1,B0,B1 = 73728

// ---------------- device scratch ----------------
__device__ __half g_C [B_TOT * K2];               // 16 MB expanded activation
__device__ __half g_Wt[OFEAT * K2];               // 4 MB  W transposed, K-major
__device__ float  g_part[KSPLIT * B_TOT * OFEAT]; // 8 MB  split-K partials

// ---------------- PTX helpers ----------------
static __device__ __forceinline__ uint32_t smem_u32(const void* p) {
    uint32_t a;
    asm("{ .reg .u64 t; cvta.to.shared.u64 t, %1; cvt.u32.u64 %0, t; }" : "=r"(a) : "l"(p));
    return a;
}
static __device__ __forceinline__ void cp16(uint32_t dst, const void* src) {
    asm volatile("cp.async.ca.shared.global [%0], [%1], 16;\n" :: "r"(dst), "l"(src));
}
#define CP_COMMIT()  asm volatile("cp.async.commit_group;" ::: "memory")
#define CP_WAIT(n)   asm volatile("cp.async.wait_group %0;" :: "n"(n) : "memory")

static __device__ __forceinline__ void ldm_x4(uint32_t* r, uint32_t addr) {
    asm volatile("ldmatrix.sync.aligned.m8n8.x4.shared.b16 {%0,%1,%2,%3}, [%4];"
                 : "=r"(r[0]), "=r"(r[1]), "=r"(r[2]), "=r"(r[3]) : "r"(addr));
}
static __device__ __forceinline__ void mma16816(float* d, const uint32_t* a,
                                                const uint32_t* b) {
    asm volatile(
        "mma.sync.aligned.m16n8k16.row.col.f32.f16.f16.f32 "
        "{%0,%1,%2,%3}, {%4,%5,%6,%7}, {%8,%9}, {%0,%1,%2,%3};"
        : "+f"(d[0]), "+f"(d[1]), "+f"(d[2]), "+f"(d[3])
        : "r"(a[0]), "r"(a[1]), "r"(a[2]), "r"(a[3]), "r"(b[0]), "r"(b[1]));
}

// ---------------------------------------------------------------------------
// Kernel 1: fused LayerNorm + expanded-activation build (one block per row)
// ---------------------------------------------------------------------------
__global__ __launch_bounds__(IFEAT) void ln_build(
    const float* __restrict__ x,
    const float* __restrict__ gamma,
    const float* __restrict__ beta)
{
    const int b = blockIdx.x;
    const int t = threadIdx.x;
    __shared__ float red[IFEAT / 32];

    float v = x[b * IFEAT + t];

    float s = v;
    #pragma unroll
    for (int o = 16; o > 0; o >>= 1) s += __shfl_xor_sync(0xFFFFFFFFu, s, o);
    if ((t & 31) == 0) red[t >> 5] = s;
    __syncthreads();
    float tot = 0.f;
    #pragma unroll
    for (int w = 0; w < IFEAT / 32; w++) tot += red[w];
    const float mu = tot * (1.0f / IFEAT);
    __syncthreads();

    const float d = v - mu;
    float s2 = d * d;
    #pragma unroll
    for (int o = 16; o > 0; o >>= 1) s2 += __shfl_xor_sync(0xFFFFFFFFu, s2, o);
    if ((t & 31) == 0) red[t >> 5] = s2;
    __syncthreads();
    float tv = 0.f;
    #pragma unroll
    for (int w = 0; w < IFEAT / 32; w++) tv += red[w];
    const float var = tv * (1.0f / IFEAT);

    const float xn = d * rsqrtf(var + LN_EPS) * gamma[t] + beta[t];

    // zero this C row (4096 half = 512 uint4)
    uint4 z; z.x = z.y = z.z = z.w = 0u;
    uint4* row = (uint4*)(g_C + (size_t)b * K2);
    row[t] = z;
    row[t + 256] = z;
    __syncthreads();

    // scatter: xn into A-block slot, 1.0 into B-block slot
    float fi = fminf(fmaxf((xn + 1.0f) * 4.0f, 0.0f), 7.0f);
    const int seg = (int)fi;
    g_C[(size_t)b * K2 + t * NSEG + seg]         = __float2half_rn(xn);
    g_C[(size_t)b * K2 + VOCAB + t * NSEG + seg] = __float2half_rn(1.0f);
}

// ---------------------------------------------------------------------------
// Kernel 2: W = [A; B] (4096 x 512 fp32) -> g_Wt (512 x 4096 fp16, K-major)
// ---------------------------------------------------------------------------
__global__ __launch_bounds__(256) void transpose_w(
    const float* __restrict__ Aw, const float* __restrict__ Bw)
{
    __shared__ float tile[32][33];
    const int v0 = blockIdx.x * 32;
    const int o0 = blockIdx.y * 32;
    const int tx = threadIdx.x;
    const int ty = threadIdx.y;

    #pragma unroll
    for (int k = 0; k < 4; k++) {
        const int v = v0 + ty + k * 8;
        const float* src = (v < VOCAB) ? (Aw + (size_t)v * OFEAT)
                                       : (Bw + (size_t)(v - VOCAB) * OFEAT);
        tile[ty + k * 8][tx] = src[o0 + tx];
    }
    __syncthreads();
    #pragma unroll
    for (int k = 0; k < 4; k++) {
        const int o = o0 + ty + k * 8;
        g_Wt[(size_t)o * K2 + v0 + tx] = __float2half_rn(tile[tx][ty + k * 8]);
    }
}

// ---------------------------------------------------------------------------
// Kernel 3: fp16 GEMM via mma.sync.m16n8k16 + cp.async double buffering.
//   y_part[kz] = C[:, kz*2048 : +2048] @ Wt[:, same]^T
// CTA 128x128, 8 warps (warp tile 32x64), grid (16, 4, 2).
// ---------------------------------------------------------------------------
__global__ __launch_bounds__(GT, 1) void gemm_kernel()
{
    extern __shared__ char dsm[];
    const uint32_t sbase = smem_u32(dsm);
    const uint32_t sA[2] = { sbase,                   sbase + STAGE_BYTES };
    const uint32_t sB[2] = { sbase + 2 * STAGE_BYTES, sbase + 3 * STAGE_BYTES };

    const int tid  = threadIdx.x;
    const int wrp  = tid >> 5;
    const int lane = tid & 31;
    const int wm   = wrp & 3;        // 4 warps over M
    const int wn   = wrp >> 2;       // 2 warps over N

    const int m0 = blockIdx.x * TM;
    const int n0 = blockIdx.y * TN;
    const int kz = blockIdx.z;
    const int k0 = kz * KCTA;

    float d[2][8][4];
    #pragma unroll
    for (int i = 0; i < 2; i++)
        #pragma unroll
        for (int j = 0; j < 8; j++)
            #pragma unroll
            for (int q = 0; q < 4; q++) d[i][j][q] = 0.f;

    // fill one stage: A 128x64 halves, B 128x64 halves, 16B chunks
    #define FILL(sidx, panel) do {                                                  \
        const int kk = k0 + (panel) * KP;                                           \
        _Pragma("unroll")                                                           \
        for (int j = 0; j < 4; j++) {                                               \
            const int idx = tid + j * GT;          /* 0..1023 */                    \
            const int r = idx >> 3, c = idx & 7;                                    \
            cp16(sA[sidx] + r * AS_STRIDE_B + c * 16,                               \
                 g_C + (size_t)(m0 + r) * K2 + kk + c * 8);                         \
        }                                                                           \
        _Pragma("unroll")                                                           \
        for (int j = 0; j < 4; j++) {                                               \
            const int idx = tid + j * GT;                                           \
            const int r = idx >> 3, c = idx & 7;                                    \
            cp16(sB[sidx] + r * AS_STRIDE_B + c * 16,                               \
                 g_Wt + (size_t)(n0 + r) * K2 + kk + c * 8);                        \
        }                                                                           \
        CP_COMMIT();                                                                \
    } while (0)

    FILL(0, 0);
    FILL(1, 1);

    // ldmatrix lane-address components (constant across panels)
    const int a_row = (lane & 15);                 // + fm*16 + wm*32
    const int a_col = (lane >> 4) << 3;            // 0 or 8 (+ kk)
    const int b_row = (lane & 7) + ((lane >> 4) << 3);   // n within 16-group
    const int b_col = ((lane >> 3) & 1) << 3;      // 0 or 8 (+ kk)

    for (int p = 0; p < NP; p++) {
        const int s = p & 1;
        if (p == NP - 1) { CP_WAIT(0); } else { CP_WAIT(1); }
        __syncthreads();

        const uint32_t aBase = sA[s];
        const uint32_t bBase = sB[s];
        #pragma unroll
        for (int ks = 0; ks < 4; ks++) {
            const int kk = ks * 16;
            uint32_t ar[2][4];
            #pragma unroll
            for (int fm = 0; fm < 2; fm++) {
                const uint32_t addr = aBase
                    + (uint32_t)(wm * 32 + fm * 16 + a_row) * AS_STRIDE_B
                    + (uint32_t)(kk + a_col) * 2;
                ldm_x4(ar[fm], addr);
            }
            uint32_t br[4][4];
            #pragma unroll
            for (int nt = 0; nt < 4; nt++) {
                const uint32_t addr = bBase
                    + (uint32_t)(wn * 64 + nt * 16 + b_row) * AS_STRIDE_B
                    + (uint32_t)(kk + b_col) * 2;
                ldm_x4(br[nt], addr);
            }
            #pragma unroll
            for (int fm = 0; fm < 2; fm++)
                #pragma unroll
                for (int nt = 0; nt < 4; nt++) {
                    mma16816(d[fm][nt * 2 + 0], ar[fm], &br[nt][0]);
                    mma16816(d[fm][nt * 2 + 1], ar[fm], &br[nt][2]);
                }
        }
        __syncthreads();
        if (p + 2 < NP) FILL(s, p + 2);
    }

    // epilogue -> g_part[kz]
    float* out = g_part + (size_t)kz * B_TOT * OFEAT;
    const int rbase = m0 + wm * 32 + (lane >> 2);
    const int cbase = n0 + wn * 64 + (lane & 3) * 2;
    #pragma unroll
    for (int fm = 0; fm < 2; fm++)
        #pragma unroll
        for (int nn = 0; nn < 8; nn++) {
            const int r = rbase + fm * 16;
            const int c = cbase + nn * 8;
            *(float2*)(out + (size_t)r * OFEAT + c)       = make_float2(d[fm][nn][0], d[fm][nn][1]);
            *(float2*)(out + (size_t)(r + 8) * OFEAT + c) = make_float2(d[fm][nn][2], d[fm][nn][3]);
        }
    #undef FILL
}

// ---------------------------------------------------------------------------
// Kernel 4: reduce split-K partials into y (deterministic)
// ---------------------------------------------------------------------------
__global__ __launch_bounds__(256) void reduce_kernel(float* __restrict__ y)
{
    const int i = blockIdx.x * 256 + threadIdx.x;          // float4 index
    const float4 a = ((const float4*)g_part)[i];
    const float4 b = ((const float4*)(g_part + B_TOT * OFEAT))[i];
    float4 o;
    o.x = a.x + b.x; o.y = a.y + b.y; o.z = a.z + b.z; o.w = a.w + b.w;
    ((float4*)y)[i] = o;
}

// ---------------------------------------------------------------------------
// Launch
// ---------------------------------------------------------------------------
extern "C" void kernel_launch(void* const* d_in, const int* in_sizes, int n_in,
                              void* d_out, int out_size)
{
    const float* x     = (const float*)d_in[0];
    const float* a_w   = (const float*)d_in[1];
    const float* b_w   = (const float*)d_in[2];
    const float* gamma = (const float*)d_in[3];
    const float* beta  = (const float*)d_in[4];
    float* y = (float*)d_out;

    cudaFuncSetAttribute(gemm_kernel, cudaFuncAttributeMaxDynamicSharedMemorySize,
                         SMEM_TOTAL);

    ln_build<<<B_TOT, IFEAT>>>(x, gamma, beta);
    transpose_w<<<dim3(K2 / 32, OFEAT / 32), dim3(32, 8)>>>(a_w, b_w);
    gemm_kernel<<<dim3(B_TOT / TM, OFEAT / TN, KSPLIT), GT, SMEM_TOTAL>>>();
    reduce_kernel<<<(B_TOT * OFEAT / 4) / 256, 256>>>(y);
}